// round 13
// baseline (speedup 1.0000x reference)
#include <cuda_runtime.h>
#include <cuda_bf16.h>
#include <cstdint>

// Problem constants
#define BB 16
#define DIM 64
#define KNUM 4
#define HH 256
#define WW 256
#define KS 5
#define HO 127
#define WO 127
#define NPIX (HO*WO)             // 16129
#define OUT_OFS (BB*DIM*HO*WO)

// Joint K-packing with bank-aware tap permutation (identical to round 12):
// 4 ics per stage -> 100 taps -> 13 k8-steps; per (s,h) slot:
//   tig0/1 = even tap on icl pair (PICF residues 0/16 mod 32)
//   tig2/3 = odd  tap on icl pair
#define GIC 4
#define NST 16                   // stages (64 ic / 4)
#define NKS 13                   // k-steps per stage
#define PSTR 37                  // patch row stride (odd -> parity trick)
// Big-tile geometry: block = 512 px (32 rows x 16 cols), 64 oc; 8 warps all-M.
#define TW 16
#define TH 32
#define PROWS 67                 // input rows per patch (2*32+3)
#define PCOLS 35                 // input cols per patch
#define PCELLS (PROWS*PCOLS)     // 2345
#define PICF 2480                // floats per ic patch (67*37=2479, pad 1; 2480%32==16)
#define PBUF (GIC*PICF)          // 9920 floats per patch buffer
#define WBUF (NKS*64*4*2)        // 6656 floats per weight buffer [s][oc][tig][h]
#define SMEM_FLOATS (2*WBUF + 2*PBUF)   // 33152
#define SMEM_BYTES (SMEM_FLOATS*4)      // 132608
#define NSLOT 10                 // ceil(2345/256)

// ---------------- device scratch ----------------
__device__ float g_pooled[BB*DIM];
__device__ float g_att[BB*KNUM];
// joint-packed tf32 weights: [b][stage][s][oc][tig][h]
__device__ __align__(16) float g_wt[(size_t)BB*NST*WBUF];

__device__ __forceinline__ uint32_t smem_u32(const void* p) {
    uint32_t a;
    asm("{ .reg .u64 t; cvta.to.shared.u64 t, %1; cvt.u32.u64 %0, t; }" : "=r"(a) : "l"(p));
    return a;
}
__device__ __forceinline__ void cp_async4(uint32_t dst, const void* src, int src_sz) {
    asm volatile("cp.async.ca.shared.global [%0], [%1], 4, %2;"
                 :: "r"(dst), "l"(src), "r"(src_sz) : "memory");
}
__device__ __forceinline__ void cp_async16(uint32_t dst, const void* src) {
    asm volatile("cp.async.cg.shared.global [%0], [%1], 16;"
                 :: "r"(dst), "l"(src) : "memory");
}
__device__ __forceinline__ uint32_t cvt_tf32(uint32_t v) {
    uint32_t o;
    asm("cvt.rna.tf32.f32 %0, %1;" : "=r"(o) : "f"(__uint_as_float(v)));
    return o;
}

// slot (s, h, tig) -> (icl, tap); false = pad (zero weight)
__device__ __forceinline__ bool slot_map(int s, int h, int tig, int& icl, int& tap) {
    int j = 2*s + h;                         // 0..25
    if (tig < 2) {                           // even-tap side
        int e = (j < 13) ? j : (j - 13);
        tap = 2*e;
        icl = ((j < 13) ? 0 : 2) + tig;
        return true;
    }
    if (j < 12)  { tap = 2*j + 1;        icl = (tig - 2);     return true; }
    if (j < 24)  { tap = 2*(j - 12) + 1; icl = 2 + (tig - 2); return true; }
    return false;                            // pad slots (s=12, tig 2/3)
}

// ---------------- K1: global average pool ----------------
__global__ void pool_kernel(const float* __restrict__ x) {
    int bc = blockIdx.x;
    const float* p = x + (size_t)bc * (HH*WW);
    float s = 0.f;
    for (int i = threadIdx.x; i < HH*WW; i += 256) s += p[i];
    __shared__ float red[256];
    red[threadIdx.x] = s;
    __syncthreads();
    for (int off = 128; off > 0; off >>= 1) {
        if (threadIdx.x < off) red[threadIdx.x] += red[threadIdx.x + off];
        __syncthreads();
    }
    if (threadIdx.x == 0) g_pooled[bc] = red[0] * (1.f / (HH*WW));
}

// ---------------- K2: attention ----------------
__global__ void att_kernel(const float* __restrict__ fc1_w, const float* __restrict__ fc1_b,
                           const float* __restrict__ fc2_w, const float* __restrict__ fc2_b) {
    int tid = threadIdx.x;
    int b = tid >> 2, k = tid & 3;
    __shared__ float a_s[BB][KNUM];
    __shared__ float l_s[BB][KNUM];
    float acc = fc1_b[k];
    #pragma unroll 8
    for (int c = 0; c < DIM; c++) acc += g_pooled[b*DIM + c] * fc1_w[k*DIM + c];
    a_s[b][k] = fmaxf(acc, 0.f);
    __syncthreads();
    float l = fc2_b[k];
    #pragma unroll
    for (int j = 0; j < KNUM; j++) l += a_s[b][j] * fc2_w[k*KNUM + j];
    l_s[b][k] = l;
    __syncthreads();
    float m = l_s[b][0];
    #pragma unroll
    for (int j = 1; j < KNUM; j++) m = fmaxf(m, l_s[b][j]);
    float den = 0.f;
    #pragma unroll
    for (int j = 0; j < KNUM; j++) den += expf(l_s[b][j] - m);
    g_att[b*KNUM + k] = expf(l - m) / den;
}

// ---------------- K3: joint weight pack (permuted) + fused w_ret ----------------
// idx = ((((b*NST + gr)*NKS + s)*64 + oc)*4 + tig)*2 + h   (identical to round 12)
__global__ void wt_fill_kernel(const float* __restrict__ weight, float* __restrict__ out) {
    int idx = blockIdx.x * 256 + threadIdx.x;     // BB*NST*WBUF = 1,703,936
    int h   = idx & 1;
    int tig = (idx >> 1) & 3;
    int oc  = (idx >> 3) & 63;
    int t   = idx >> 9;
    int s   = t % NKS;
    t /= NKS;
    int gr  = t & 15;
    int b   = t >> 4;
    int icl, tap;
    uint32_t bits = 0u;
    if (slot_map(s, h, tig, icl, tap)) {
        int ic = gr*GIC + icl;
        float v = 0.f;
        #pragma unroll
        for (int k = 0; k < KNUM; k++)
            v += g_att[b*KNUM + k] * weight[(((size_t)k*64 + oc)*64 + ic)*25 + tap];
        asm("cvt.rna.tf32.f32 %0, %1;" : "=r"(bits) : "f"(v));
        out[OUT_OFS + (((size_t)b*64 + oc)*25 + tap)*64 + ic] = v;
    }
    *(uint32_t*)&g_wt[idx] = bits;
}

// ---------------- K4: tf32 mma.sync implicit-GEMM conv, big-tile ----------------
// 1 CTA/SM, 256 thr = 8 warps all along M. Block: 32x16 = 512 px, 64 oc.
// Warp tile: 64 px x 64 oc = 4 m16 x 8 n8 tiles (128 acc regs, 255-reg budget).
// 16 stages of 4 ics; 13 k8-steps per stage; conflict-free A via tap permutation.
__global__ __launch_bounds__(256, 1)
void conv_mma_kernel(const float* __restrict__ x, const float* __restrict__ bias,
                     float* __restrict__ out) {
    extern __shared__ __align__(16) float sm[];
    float* s_w = sm;                 // [2][WBUF]
    float* s_p = sm + 2*WBUF;        // [2][PBUF]
    __shared__ float s_bias[64];

    const int tid  = threadIdx.x;
    const int lane = tid & 31;
    const int wid  = tid >> 5;
    const int g    = lane >> 2;
    const int tig  = lane & 3;

    const int b   = blockIdx.z;
    const int ox0 = blockIdx.x * TW;
    const int oy0 = blockIdx.y * TH;

    if (tid < 64) {
        float v = 0.f;
        #pragma unroll
        for (int k = 0; k < KNUM; k++) v += g_att[b*KNUM + k] * bias[k*64 + tid];
        s_bias[tid] = v;
    }
    // zero patch cells cp.async never writes (pad cols 35/36, chunk tail)
    for (int i = tid; i < 2*PBUF; i += 256) {
        int m = i % PICF;
        if (m >= PROWS*PSTR - 2 || (m % PSTR) >= PCOLS) s_p[i] = 0.f;
    }

    const int iy0 = 2*oy0 - 1, ix0 = 2*ox0 - 1;
    const float* xb = x + (size_t)b * DIM * (HH*WW);
    const uint32_t p_base = smem_u32(s_p);
    const uint32_t w_base = smem_u32(s_w);

    // staging slots, packed: soff/goff 16-bit pairs + validity mask
    uint32_t sP[NSLOT/2], gP[NSLOT/2], vmask = 0;
    #pragma unroll
    for (int j = 0; j < NSLOT; j++) {
        int i = tid + j*256;
        bool on = (i < PCELLS);
        int r = i / PCOLS, c = i % PCOLS;
        if (!on) { r = 0; c = 35; }           // park in pad column (zero-fill benign)
        int gy = iy0 + r, gx = ix0 + c;
        bool valid = on && (unsigned)gy < (unsigned)HH && (unsigned)gx < (unsigned)WW;
        uint32_t so = (uint32_t)(r*PSTR + c);
        uint32_t go = valid ? (uint32_t)(gy*WW + gx) : 0u;
        if (j & 1) { sP[j>>1] |= so << 16; gP[j>>1] |= go << 16; }
        else       { sP[j>>1]  = so;       gP[j>>1]  = go; }
        if (valid) vmask |= 1u << j;
    }

    // packed A offsets per k-step: low16 = h0, high16 = h1
    uint32_t offP[NKS];
    #pragma unroll
    for (int s = 0; s < NKS; s++) {
        int o2[2];
        #pragma unroll
        for (int h = 0; h < 2; h++) {
            int icl, tap, off;
            if (slot_map(s, h, tig, icl, tap))
                off = icl*PICF + (tap/5)*PSTR + (tap%5);
            else
                off = (tig == 2) ? 1 : 17;    // pad: odd residues, harmless reads
            o2[h] = off;
        }
        offP[s] = (uint32_t)o2[0] | ((uint32_t)o2[1] << 16);
    }

    // A row bases: m16 tile mt covers output row (wid*4 + mt), cols 0..15
    int base0[4];
    #pragma unroll
    for (int mt = 0; mt < 4; mt++)
        base0[mt] = (wid*4 + mt)*2*PSTR + 2*g;

    float acc[4][8][4];
    #pragma unroll
    for (int mt = 0; mt < 4; mt++)
        #pragma unroll
        for (int nt = 0; nt < 8; nt++)
            #pragma unroll
            for (int r = 0; r < 4; r++) acc[mt][nt][r] = 0.f;

    auto stage = [&](int gr, int bufi) {
        const float4* ws = (const float4*)(g_wt + ((size_t)(b*NST + gr))*WBUF);
        const uint32_t wdst = w_base + (uint32_t)bufi*(WBUF*4);
        for (int i = tid; i < WBUF/4; i += 256)     // 1664 float4
            cp_async16(wdst + (uint32_t)i*16u, ws + i);
        #pragma unroll
        for (int j = 0; j < NSLOT; j++) {
            uint32_t so = (sP[j>>1] >> ((j&1)*16)) & 0xFFFFu;
            uint32_t go = (gP[j>>1] >> ((j&1)*16)) & 0xFFFFu;
            int sz = ((vmask >> j) & 1u) ? 4 : 0;
            uint32_t d0 = p_base + (uint32_t)bufi*(PBUF*4) + so*4u;
            #pragma unroll
            for (int icl = 0; icl < GIC; icl++)
                cp_async4(d0 + (uint32_t)icl*(PICF*4),
                          xb + (size_t)(gr*GIC + icl)*(HH*WW) + go, sz);
        }
        asm volatile("cp.async.commit_group;" ::: "memory");
    };

    stage(0, 0);
    asm volatile("cp.async.wait_group 0;" ::: "memory");
    __syncthreads();

    for (int gr = 0; gr < NST; gr++) {
        const int cur = gr & 1;
        if (gr + 1 < NST) stage(gr + 1, cur ^ 1);

        const float* wbuf = s_w + cur*WBUF;
        const float* pbuf = s_p + cur*PBUF;
        #pragma unroll
        for (int s = 0; s < NKS; s++) {
            // B fragments: [s][oc][tig][h], oc = nt*8 + g; coalesced LDS.64
            const float* wr = wbuf + ((s*64 + g)*4 + tig)*2;
            uint32_t b0[8], b1[8];
            #pragma unroll
            for (int nt = 0; nt < 8; nt++) {
                float2 w2 = *(const float2*)&wr[nt*64];
                b0[nt] = __float_as_uint(w2.x);
                b1[nt] = __float_as_uint(w2.y);
            }
            const int o0 = (int)(offP[s] & 0xFFFFu);
            const int o1 = (int)(offP[s] >> 16);
            #pragma unroll
            for (int mt = 0; mt < 4; mt++) {
                uint32_t a0 = cvt_tf32(*(const uint32_t*)&pbuf[base0[mt] + o0]);
                uint32_t a1 = cvt_tf32(*(const uint32_t*)&pbuf[base0[mt] + 16 + o0]);
                uint32_t a2 = cvt_tf32(*(const uint32_t*)&pbuf[base0[mt] + o1]);
                uint32_t a3 = cvt_tf32(*(const uint32_t*)&pbuf[base0[mt] + 16 + o1]);
                #pragma unroll
                for (int nt = 0; nt < 8; nt++) {
                    asm volatile(
                        "mma.sync.aligned.m16n8k8.row.col.f32.tf32.tf32.f32 "
                        "{%0,%1,%2,%3}, {%4,%5,%6,%7}, {%8,%9}, {%0,%1,%2,%3};"
                        : "+f"(acc[mt][nt][0]), "+f"(acc[mt][nt][1]),
                          "+f"(acc[mt][nt][2]), "+f"(acc[mt][nt][3])
                        : "r"(a0), "r"(a1), "r"(a2), "r"(a3), "r"(b0[nt]), "r"(b1[nt]));
                }
            }
        }
        asm volatile("cp.async.wait_group 0;" ::: "memory");
        __syncthreads();
    }

    // ---- writeout: m16 tile mt = output row (wid*4+mt); frag rows g/g+8 = cols ----
    #pragma unroll
    for (int mt = 0; mt < 4; mt++) {
        const int oy = oy0 + wid*4 + mt;
        #pragma unroll
        for (int nt = 0; nt < 8; nt++) {
            const int oc = nt*8 + 2*tig;
            const float bz0 = s_bias[oc], bz1 = s_bias[oc + 1];
            #pragma unroll
            for (int h = 0; h < 2; h++) {
                const int ox = ox0 + g + 8*h;
                if (oy < HO && ox < WO) {
                    size_t o_idx = ((size_t)(b*64 + oc))*NPIX + (size_t)oy*WO + ox;
                    out[o_idx]        = acc[mt][nt][2*h]     + bz0;
                    out[o_idx + NPIX] = acc[mt][nt][2*h + 1] + bz1;
                }
            }
        }
    }
}

extern "C" void kernel_launch(void* const* d_in, const int* in_sizes, int n_in,
                              void* d_out, int out_size) {
    const float* x      = (const float*)d_in[0];
    const float* fc1_w  = (const float*)d_in[1];
    const float* fc1_b  = (const float*)d_in[2];
    const float* fc2_w  = (const float*)d_in[3];
    const float* fc2_b  = (const float*)d_in[4];
    const float* weight = (const float*)d_in[5];
    const float* bias   = (const float*)d_in[6];
    float* out = (float*)d_out;

    cudaFuncSetAttribute(conv_mma_kernel,
                         cudaFuncAttributeMaxDynamicSharedMemorySize, SMEM_BYTES);

    pool_kernel<<<BB*DIM, 256>>>(x);
    att_kernel<<<1, 64>>>(fc1_w, fc1_b, fc2_w, fc2_b);
    wt_fill_kernel<<<(BB*NST*WBUF)/256, 256>>>(weight, out);
    dim3 grid((WO + TW - 1)/TW, (HO + TH - 1)/TH, BB);
    conv_mma_kernel<<<grid, 256, SMEM_BYTES>>>(x, bias, out);
}

// round 14
// speedup vs baseline: 1.1050x; 1.1050x over previous
#include <cuda_runtime.h>
#include <cuda_bf16.h>
#include <cstdint>

// Problem constants
#define BB 16
#define DIM 64
#define KNUM 4
#define HH 256
#define WW 256
#define KS 5
#define HO 127
#define WO 127
#define NPIX (HO*WO)             // 16129
#define OUT_OFS (BB*DIM*HO*WO)

// Joint K-packing with bank-aware tap permutation (identical math to r12/r13):
// 4 ics per stage -> 100 taps -> 13 k8-steps; per (s,h) slot:
//   tig0/1 = even tap on icl pair (PICF residues 0/16 mod 32)
//   tig2/3 = odd  tap on icl pair
#define GIC 4
#define NST 16                   // stages (64 ic / 4)
#define NKS 13                   // k-steps per stage
#define PSTR 37                  // patch row stride (odd -> parity trick)
// Geometry: block = 256 px (16 rows x 16 cols), 64 oc; 8 warps all-M.
// Warp tile: 32 px x 64 oc = 2 m16 x 8 n8 (64 acc regs). Grid 1024 -> tail 1.2%.
#define TW 16
#define TH 16
#define PROWS 35                 // input rows per patch (2*16+3)
#define PCOLS 35                 // input cols per patch
#define PCELLS (PROWS*PCOLS)     // 1225
#define PICF 1296                // floats per ic patch (35*37=1295, pad 1; 1296%32==16)
#define PBUF (GIC*PICF)          // 5184 floats per patch buffer
#define WBUF (NKS*64*4*2)        // 6656 floats per weight buffer [s][oc][tig][h]
#define SMEM_FLOATS (2*WBUF + 2*PBUF)   // 23680
#define SMEM_BYTES (SMEM_FLOATS*4)      // 94720
#define NSLOT 5                  // ceil(1225/256)

// ---------------- device scratch ----------------
__device__ float g_pooled[BB*DIM];
__device__ float g_att[BB*KNUM];
// joint-packed tf32 weights: [b][stage][s][oc][tig][h]
__device__ __align__(16) float g_wt[(size_t)BB*NST*WBUF];

__device__ __forceinline__ uint32_t smem_u32(const void* p) {
    uint32_t a;
    asm("{ .reg .u64 t; cvta.to.shared.u64 t, %1; cvt.u32.u64 %0, t; }" : "=r"(a) : "l"(p));
    return a;
}
__device__ __forceinline__ void cp_async4(uint32_t dst, const void* src, int src_sz) {
    asm volatile("cp.async.ca.shared.global [%0], [%1], 4, %2;"
                 :: "r"(dst), "l"(src), "r"(src_sz) : "memory");
}
__device__ __forceinline__ void cp_async16(uint32_t dst, const void* src) {
    asm volatile("cp.async.cg.shared.global [%0], [%1], 16;"
                 :: "r"(dst), "l"(src) : "memory");
}
__device__ __forceinline__ uint32_t cvt_tf32(uint32_t v) {
    uint32_t o;
    asm("cvt.rna.tf32.f32 %0, %1;" : "=r"(o) : "f"(__uint_as_float(v)));
    return o;
}

// slot (s, h, tig) -> (icl, tap); false = pad (zero weight)
__device__ __forceinline__ bool slot_map(int s, int h, int tig, int& icl, int& tap) {
    int j = 2*s + h;                         // 0..25
    if (tig < 2) {                           // even-tap side
        int e = (j < 13) ? j : (j - 13);
        tap = 2*e;
        icl = ((j < 13) ? 0 : 2) + tig;
        return true;
    }
    if (j < 12)  { tap = 2*j + 1;        icl = (tig - 2);     return true; }
    if (j < 24)  { tap = 2*(j - 12) + 1; icl = 2 + (tig - 2); return true; }
    return false;                            // pad slots (s=12, tig 2/3)
}

// ---------------- K1: global average pool ----------------
__global__ void pool_kernel(const float* __restrict__ x) {
    int bc = blockIdx.x;
    const float* p = x + (size_t)bc * (HH*WW);
    float s = 0.f;
    for (int i = threadIdx.x; i < HH*WW; i += 256) s += p[i];
    __shared__ float red[256];
    red[threadIdx.x] = s;
    __syncthreads();
    for (int off = 128; off > 0; off >>= 1) {
        if (threadIdx.x < off) red[threadIdx.x] += red[threadIdx.x + off];
        __syncthreads();
    }
    if (threadIdx.x == 0) g_pooled[bc] = red[0] * (1.f / (HH*WW));
}

// ---------------- K2: attention ----------------
__global__ void att_kernel(const float* __restrict__ fc1_w, const float* __restrict__ fc1_b,
                           const float* __restrict__ fc2_w, const float* __restrict__ fc2_b) {
    int tid = threadIdx.x;
    int b = tid >> 2, k = tid & 3;
    __shared__ float a_s[BB][KNUM];
    __shared__ float l_s[BB][KNUM];
    float acc = fc1_b[k];
    #pragma unroll 8
    for (int c = 0; c < DIM; c++) acc += g_pooled[b*DIM + c] * fc1_w[k*DIM + c];
    a_s[b][k] = fmaxf(acc, 0.f);
    __syncthreads();
    float l = fc2_b[k];
    #pragma unroll
    for (int j = 0; j < KNUM; j++) l += a_s[b][j] * fc2_w[k*KNUM + j];
    l_s[b][k] = l;
    __syncthreads();
    float m = l_s[b][0];
    #pragma unroll
    for (int j = 1; j < KNUM; j++) m = fmaxf(m, l_s[b][j]);
    float den = 0.f;
    #pragma unroll
    for (int j = 0; j < KNUM; j++) den += expf(l_s[b][j] - m);
    g_att[b*KNUM + k] = expf(l - m) / den;
}

// ---------------- K3: joint weight pack (permuted) + fused w_ret ----------------
// idx = ((((b*NST + gr)*NKS + s)*64 + oc)*4 + tig)*2 + h   (identical to r12/r13)
__global__ void wt_fill_kernel(const float* __restrict__ weight, float* __restrict__ out) {
    int idx = blockIdx.x * 256 + threadIdx.x;     // BB*NST*WBUF = 1,703,936
    int h   = idx & 1;
    int tig = (idx >> 1) & 3;
    int oc  = (idx >> 3) & 63;
    int t   = idx >> 9;
    int s   = t % NKS;
    t /= NKS;
    int gr  = t & 15;
    int b   = t >> 4;
    int icl, tap;
    uint32_t bits = 0u;
    if (slot_map(s, h, tig, icl, tap)) {
        int ic = gr*GIC + icl;
        float v = 0.f;
        #pragma unroll
        for (int k = 0; k < KNUM; k++)
            v += g_att[b*KNUM + k] * weight[(((size_t)k*64 + oc)*64 + ic)*25 + tap];
        asm("cvt.rna.tf32.f32 %0, %1;" : "=r"(bits) : "f"(v));
        out[OUT_OFS + (((size_t)b*64 + oc)*25 + tap)*64 + ic] = v;
    }
    *(uint32_t*)&g_wt[idx] = bits;
}

// ---------------- K4: tf32 mma.sync implicit-GEMM conv ----------------
// 1 CTA 256 thr = 8 warps all along M. Block: 16x16 = 256 px, 64 oc.
// Warp tile: 32 px x 64 oc = 2 m16 x 8 n8 (64 acc regs). Grid 1024 (tail 1.2%).
// 16 stages of 4 ics; 13 k8-steps/stage; conflict-free A via tap permutation.
__global__ __launch_bounds__(256, 1)
void conv_mma_kernel(const float* __restrict__ x, const float* __restrict__ bias,
                     float* __restrict__ out) {
    extern __shared__ __align__(16) float sm[];
    float* s_w = sm;                 // [2][WBUF]
    float* s_p = sm + 2*WBUF;        // [2][PBUF]
    __shared__ float s_bias[64];

    const int tid  = threadIdx.x;
    const int lane = tid & 31;
    const int wid  = tid >> 5;
    const int g    = lane >> 2;
    const int tig  = lane & 3;

    const int b   = blockIdx.z;
    const int ox0 = blockIdx.x * TW;
    const int oy0 = blockIdx.y * TH;

    if (tid < 64) {
        float v = 0.f;
        #pragma unroll
        for (int k = 0; k < KNUM; k++) v += g_att[b*KNUM + k] * bias[k*64 + tid];
        s_bias[tid] = v;
    }
    // zero patch cells cp.async never writes (pad cols 35/36, chunk tail)
    for (int i = tid; i < 2*PBUF; i += 256) {
        int m = i % PICF;
        if (m >= PROWS*PSTR - 2 || (m % PSTR) >= PCOLS) s_p[i] = 0.f;
    }

    const int iy0 = 2*oy0 - 1, ix0 = 2*ox0 - 1;
    const float* xb = x + (size_t)b * DIM * (HH*WW);
    const uint32_t p_base = smem_u32(s_p);
    const uint32_t w_base = smem_u32(s_w);

    // staging slots, packed: soff/goff 16-bit pairs + validity mask
    uint32_t sP[(NSLOT+1)/2], gP[(NSLOT+1)/2], vmask = 0;
    #pragma unroll
    for (int j = 0; j < NSLOT; j++) {
        int i = tid + j*256;
        bool on = (i < PCELLS);
        int r = i / PCOLS, c = i % PCOLS;
        if (!on) { r = 0; c = 35; }           // park in pad column (zero-fill benign)
        int gy = iy0 + r, gx = ix0 + c;
        bool valid = on && (unsigned)gy < (unsigned)HH && (unsigned)gx < (unsigned)WW;
        uint32_t so = (uint32_t)(r*PSTR + c);
        uint32_t go = valid ? (uint32_t)(gy*WW + gx) : 0u;
        if (j & 1) { sP[j>>1] |= so << 16; gP[j>>1] |= go << 16; }
        else       { sP[j>>1]  = so;       gP[j>>1]  = go; }
        if (valid) vmask |= 1u << j;
    }

    // packed A offsets per k-step: low16 = h0, high16 = h1
    uint32_t offP[NKS];
    #pragma unroll
    for (int s = 0; s < NKS; s++) {
        int o2[2];
        #pragma unroll
        for (int h = 0; h < 2; h++) {
            int icl, tap, off;
            if (slot_map(s, h, tig, icl, tap))
                off = icl*PICF + (tap/5)*PSTR + (tap%5);
            else
                off = (tig == 2) ? 1 : 17;    // pad: odd residues, harmless reads
            o2[h] = off;
        }
        offP[s] = (uint32_t)o2[0] | ((uint32_t)o2[1] << 16);
    }

    // A row bases: m16 tile mt covers output row (wid*2 + mt), cols 0..15
    int base0[2];
    #pragma unroll
    for (int mt = 0; mt < 2; mt++)
        base0[mt] = (wid*2 + mt)*2*PSTR + 2*g;

    float acc[2][8][4];
    #pragma unroll
    for (int mt = 0; mt < 2; mt++)
        #pragma unroll
        for (int nt = 0; nt < 8; nt++)
            #pragma unroll
            for (int r = 0; r < 4; r++) acc[mt][nt][r] = 0.f;

    auto stage = [&](int gr, int bufi) {
        const float4* ws = (const float4*)(g_wt + ((size_t)(b*NST + gr))*WBUF);
        const uint32_t wdst = w_base + (uint32_t)bufi*(WBUF*4);
        for (int i = tid; i < WBUF/4; i += 256)     // 1664 float4
            cp_async16(wdst + (uint32_t)i*16u, ws + i);
        #pragma unroll
        for (int j = 0; j < NSLOT; j++) {
            uint32_t so = (sP[j>>1] >> ((j&1)*16)) & 0xFFFFu;
            uint32_t go = (gP[j>>1] >> ((j&1)*16)) & 0xFFFFu;
            int sz = ((vmask >> j) & 1u) ? 4 : 0;
            uint32_t d0 = p_base + (uint32_t)bufi*(PBUF*4) + so*4u;
            #pragma unroll
            for (int icl = 0; icl < GIC; icl++)
                cp_async4(d0 + (uint32_t)icl*(PICF*4),
                          xb + (size_t)(gr*GIC + icl)*(HH*WW) + go, sz);
        }
        asm volatile("cp.async.commit_group;" ::: "memory");
    };

    stage(0, 0);
    asm volatile("cp.async.wait_group 0;" ::: "memory");
    __syncthreads();

    for (int gr = 0; gr < NST; gr++) {
        const int cur = gr & 1;
        if (gr + 1 < NST) stage(gr + 1, cur ^ 1);

        const float* wbuf = s_w + cur*WBUF;
        const float* pbuf = s_p + cur*PBUF;
        #pragma unroll
        for (int s = 0; s < NKS; s++) {
            // B fragments: [s][oc][tig][h], oc = nt*8 + g; coalesced LDS.64
            const float* wr = wbuf + ((s*64 + g)*4 + tig)*2;
            uint32_t b0[8], b1[8];
            #pragma unroll
            for (int nt = 0; nt < 8; nt++) {
                float2 w2 = *(const float2*)&wr[nt*64];
                b0[nt] = __float_as_uint(w2.x);
                b1[nt] = __float_as_uint(w2.y);
            }
            const int o0 = (int)(offP[s] & 0xFFFFu);
            const int o1 = (int)(offP[s] >> 16);
            #pragma unroll
            for (int mt = 0; mt < 2; mt++) {
                uint32_t a0 = cvt_tf32(*(const uint32_t*)&pbuf[base0[mt] + o0]);
                uint32_t a1 = cvt_tf32(*(const uint32_t*)&pbuf[base0[mt] + 16 + o0]);
                uint32_t a2 = cvt_tf32(*(const uint32_t*)&pbuf[base0[mt] + o1]);
                uint32_t a3 = cvt_tf32(*(const uint32_t*)&pbuf[base0[mt] + 16 + o1]);
                #pragma unroll
                for (int nt = 0; nt < 8; nt++) {
                    asm volatile(
                        "mma.sync.aligned.m16n8k8.row.col.f32.tf32.tf32.f32 "
                        "{%0,%1,%2,%3}, {%4,%5,%6,%7}, {%8,%9}, {%0,%1,%2,%3};"
                        : "+f"(acc[mt][nt][0]), "+f"(acc[mt][nt][1]),
                          "+f"(acc[mt][nt][2]), "+f"(acc[mt][nt][3])
                        : "r"(a0), "r"(a1), "r"(a2), "r"(a3), "r"(b0[nt]), "r"(b1[nt]));
                }
            }
        }
        asm volatile("cp.async.wait_group 0;" ::: "memory");
        __syncthreads();
    }

    // ---- writeout: m16 tile mt = output row (wid*2+mt); frag rows g/g+8 = cols ----
    #pragma unroll
    for (int mt = 0; mt < 2; mt++) {
        const int oy = oy0 + wid*2 + mt;
        #pragma unroll
        for (int nt = 0; nt < 8; nt++) {
            const int oc = nt*8 + 2*tig;
            const float bz0 = s_bias[oc], bz1 = s_bias[oc + 1];
            #pragma unroll
            for (int h = 0; h < 2; h++) {
                const int ox = ox0 + g + 8*h;
                if (oy < HO && ox < WO) {
                    size_t o_idx = ((size_t)(b*64 + oc))*NPIX + (size_t)oy*WO + ox;
                    out[o_idx]        = acc[mt][nt][2*h]     + bz0;
                    out[o_idx + NPIX] = acc[mt][nt][2*h + 1] + bz1;
                }
            }
        }
    }
}

extern "C" void kernel_launch(void* const* d_in, const int* in_sizes, int n_in,
                              void* d_out, int out_size) {
    const float* x      = (const float*)d_in[0];
    const float* fc1_w  = (const float*)d_in[1];
    const float* fc1_b  = (const float*)d_in[2];
    const float* fc2_w  = (const float*)d_in[3];
    const float* fc2_b  = (const float*)d_in[4];
    const float* weight = (const float*)d_in[5];
    const float* bias   = (const float*)d_in[6];
    float* out = (float*)d_out;

    cudaFuncSetAttribute(conv_mma_kernel,
                         cudaFuncAttributeMaxDynamicSharedMemorySize, SMEM_BYTES);

    pool_kernel<<<BB*DIM, 256>>>(x);
    att_kernel<<<1, 64>>>(fc1_w, fc1_b, fc2_w, fc2_b);
    wt_fill_kernel<<<(BB*NST*WBUF)/256, 256>>>(weight, out);
    dim3 grid((WO + TW - 1)/TW, (HO + TH - 1)/TH, BB);
    conv_mma_kernel<<<grid, 256, SMEM_BYTES>>>(x, bias, out);
}

// round 17
// speedup vs baseline: 1.1485x; 1.0393x over previous
#include <cuda_runtime.h>
#include <cuda_bf16.h>
#include <cstdint>

// Problem constants
#define BB 16
#define DIM 64
#define KNUM 4
#define HH 256
#define WW 256
#define KS 5
#define HO 127
#define WO 127
#define NPIX (HO*WO)             // 16129
#define OUT_OFS (BB*DIM*HO*WO)

// Joint K-packing with bank-aware tap permutation (identical math to r12-r14):
// 4 ics per stage -> 100 taps -> 13 k8-steps; per (s,h) slot:
//   tig0/1 = even tap on icl pair (PICF residues 0/16 mod 32)
//   tig2/3 = odd  tap on icl pair
#define GIC 4
#define NST 16                   // stages (64 ic / 4)
#define NKS 13                   // k-steps per stage
#define PSTR 37                  // patch row stride (odd -> parity trick)
// Geometry (r14): block = 256 px (16x16), 64 oc; 8 warps all-M.
// Warp tile: 32 px x 64 oc = 2 m16 x 8 n8 (64 acc regs). Grid 1024 -> tail 1.2%.
// r15/r16: 2 CTAs/SM (launch_bounds (256,2)) -> 16 warps/SM to hide LDS latency.
#define TW 16
#define TH 16
#define PROWS 35                 // input rows per patch (2*16+3)
#define PCOLS 35                 // input cols per patch
#define PCELLS (PROWS*PCOLS)     // 1225
#define PICF 1296                // floats per ic patch (35*37=1295, pad 1; 1296%32==16)
#define PBUF (GIC*PICF)          // 5184 floats per patch buffer
#define WBUF (NKS*64*4*2)        // 6656 floats per weight buffer [s][oc][tig][h]
#define SMEM_FLOATS (2*WBUF + 2*PBUF)   // 23680
#define SMEM_BYTES (SMEM_FLOATS*4)      // 94720  (x2 CTAs = 189KB < 228KB)
#define NSLOT 5                  // ceil(1225/256)

// ---------------- device scratch ----------------
__device__ float g_pooled[BB*DIM];
__device__ float g_att[BB*KNUM];
// joint-packed tf32 weights: [b][stage][s][oc][tig][h]
__device__ __align__(16) float g_wt[(size_t)BB*NST*WBUF];

__device__ __forceinline__ uint32_t smem_u32(const void* p) {
    uint32_t a;
    asm("{ .reg .u64 t; cvta.to.shared.u64 t, %1; cvt.u32.u64 %0, t; }" : "=r"(a) : "l"(p));
    return a;
}
__device__ __forceinline__ void cp_async4(uint32_t dst, const void* src, int src_sz) {
    asm volatile("cp.async.ca.shared.global [%0], [%1], 4, %2;"
                 :: "r"(dst), "l"(src), "r"(src_sz) : "memory");
}
__device__ __forceinline__ void cp_async16(uint32_t dst, const void* src) {
    asm volatile("cp.async.cg.shared.global [%0], [%1], 16;"
                 :: "r"(dst), "l"(src) : "memory");
}
__device__ __forceinline__ uint32_t cvt_tf32(uint32_t v) {
    uint32_t o;
    asm("cvt.rna.tf32.f32 %0, %1;" : "=r"(o) : "f"(__uint_as_float(v)));
    return o;
}

// slot (s, h, tig) -> (icl, tap); false = pad (zero weight)
__device__ __forceinline__ bool slot_map(int s, int h, int tig, int& icl, int& tap) {
    int j = 2*s + h;                         // 0..25
    if (tig < 2) {                           // even-tap side
        int e = (j < 13) ? j : (j - 13);
        tap = 2*e;
        icl = ((j < 13) ? 0 : 2) + tig;
        return true;
    }
    if (j < 12)  { tap = 2*j + 1;        icl = (tig - 2);     return true; }
    if (j < 24)  { tap = 2*(j - 12) + 1; icl = 2 + (tig - 2); return true; }
    return false;                            // pad slots (s=12, tig 2/3)
}

// ---------------- K1: global average pool ----------------
__global__ void pool_kernel(const float* __restrict__ x) {
    int bc = blockIdx.x;
    const float* p = x + (size_t)bc * (HH*WW);
    float s = 0.f;
    for (int i = threadIdx.x; i < HH*WW; i += 256) s += p[i];
    __shared__ float red[256];
    red[threadIdx.x] = s;
    __syncthreads();
    for (int off = 128; off > 0; off >>= 1) {
        if (threadIdx.x < off) red[threadIdx.x] += red[threadIdx.x + off];
        __syncthreads();
    }
    if (threadIdx.x == 0) g_pooled[bc] = red[0] * (1.f / (HH*WW));
}

// ---------------- K2: attention ----------------
__global__ void att_kernel(const float* __restrict__ fc1_w, const float* __restrict__ fc1_b,
                           const float* __restrict__ fc2_w, const float* __restrict__ fc2_b) {
    int tid = threadIdx.x;
    int b = tid >> 2, k = tid & 3;
    __shared__ float a_s[BB][KNUM];
    __shared__ float l_s[BB][KNUM];
    float acc = fc1_b[k];
    #pragma unroll 8
    for (int c = 0; c < DIM; c++) acc += g_pooled[b*DIM + c] * fc1_w[k*DIM + c];
    a_s[b][k] = fmaxf(acc, 0.f);
    __syncthreads();
    float l = fc2_b[k];
    #pragma unroll
    for (int j = 0; j < KNUM; j++) l += a_s[b][j] * fc2_w[k*KNUM + j];
    l_s[b][k] = l;
    __syncthreads();
    float m = l_s[b][0];
    #pragma unroll
    for (int j = 1; j < KNUM; j++) m = fmaxf(m, l_s[b][j]);
    float den = 0.f;
    #pragma unroll
    for (int j = 0; j < KNUM; j++) den += expf(l_s[b][j] - m);
    g_att[b*KNUM + k] = expf(l - m) / den;
}

// ---------------- K3: joint weight pack (permuted) + fused w_ret ----------------
// idx = ((((b*NST + gr)*NKS + s)*64 + oc)*4 + tig)*2 + h   (identical to r12-r14)
__global__ void wt_fill_kernel(const float* __restrict__ weight, float* __restrict__ out) {
    int idx = blockIdx.x * 256 + threadIdx.x;     // BB*NST*WBUF = 1,703,936
    int h   = idx & 1;
    int tig = (idx >> 1) & 3;
    int oc  = (idx >> 3) & 63;
    int t   = idx >> 9;
    int s   = t % NKS;
    t /= NKS;
    int gr  = t & 15;
    int b   = t >> 4;
    int icl, tap;
    uint32_t bits = 0u;
    if (slot_map(s, h, tig, icl, tap)) {
        int ic = gr*GIC + icl;
        float v = 0.f;
        #pragma unroll
        for (int k = 0; k < KNUM; k++)
            v += g_att[b*KNUM + k] * weight[(((size_t)k*64 + oc)*64 + ic)*25 + tap];
        asm("cvt.rna.tf32.f32 %0, %1;" : "=r"(bits) : "f"(v));
        out[OUT_OFS + (((size_t)b*64 + oc)*25 + tap)*64 + ic] = v;
    }
    *(uint32_t*)&g_wt[idx] = bits;
}

// ---------------- K4: tf32 mma.sync implicit-GEMM conv ----------------
// 2 CTAs/SM, 256 thr = 8 warps all along M. Block: 16x16 = 256 px, 64 oc.
// Warp tile: 32 px x 64 oc = 2 m16 x 8 n8 (64 acc regs). Grid 1024 (tail 1.2%).
// 16 stages of 4 ics; 13 k8-steps/stage; conflict-free A via tap permutation.
__global__ __launch_bounds__(256, 2)
void conv_mma_kernel(const float* __restrict__ x, const float* __restrict__ bias,
                     float* __restrict__ out) {
    extern __shared__ __align__(16) float sm[];
    float* s_w = sm;                 // [2][WBUF]
    float* s_p = sm + 2*WBUF;        // [2][PBUF]
    __shared__ float s_bias[64];

    const int tid  = threadIdx.x;
    const int lane = tid & 31;
    const int wid  = tid >> 5;
    const int g    = lane >> 2;
    const int tig  = lane & 3;

    const int b   = blockIdx.z;
    const int ox0 = blockIdx.x * TW;
    const int oy0 = blockIdx.y * TH;

    if (tid < 64) {
        float v = 0.f;
        #pragma unroll
        for (int k = 0; k < KNUM; k++) v += g_att[b*KNUM + k] * bias[k*64 + tid];
        s_bias[tid] = v;
    }
    // zero patch cells cp.async never writes (pad cols 35/36, chunk tail)
    for (int i = tid; i < 2*PBUF; i += 256) {
        int m = i % PICF;
        if (m >= PROWS*PSTR - 2 || (m % PSTR) >= PCOLS) s_p[i] = 0.f;
    }

    const int iy0 = 2*oy0 - 1, ix0 = 2*ox0 - 1;
    const float* xb = x + (size_t)b * DIM * (HH*WW);
    const uint32_t p_base = smem_u32(s_p);
    const uint32_t w_base = smem_u32(s_w);

    // staging slots, packed: soff/goff 16-bit pairs + validity mask
    uint32_t sP[(NSLOT+1)/2], gP[(NSLOT+1)/2], vmask = 0;
    #pragma unroll
    for (int j = 0; j < NSLOT; j++) {
        int i = tid + j*256;
        bool on = (i < PCELLS);
        int r = i / PCOLS, c = i % PCOLS;
        if (!on) { r = 0; c = 35; }           // park in pad column (zero-fill benign)
        int gy = iy0 + r, gx = ix0 + c;
        bool valid = on && (unsigned)gy < (unsigned)HH && (unsigned)gx < (unsigned)WW;
        uint32_t so = (uint32_t)(r*PSTR + c);
        uint32_t go = valid ? (uint32_t)(gy*WW + gx) : 0u;
        if (j & 1) { sP[j>>1] |= so << 16; gP[j>>1] |= go << 16; }
        else       { sP[j>>1]  = so;       gP[j>>1]  = go; }
        if (valid) vmask |= 1u << j;
    }

    // packed A offsets per k-step: low16 = h0, high16 = h1
    uint32_t offP[NKS];
    #pragma unroll
    for (int s = 0; s < NKS; s++) {
        int o2[2];
        #pragma unroll
        for (int h = 0; h < 2; h++) {
            int icl, tap, off;
            if (slot_map(s, h, tig, icl, tap))
                off = icl*PICF + (tap/5)*PSTR + (tap%5);
            else
                off = (tig == 2) ? 1 : 17;    // pad: odd residues, harmless reads
            o2[h] = off;
        }
        offP[s] = (uint32_t)o2[0] | ((uint32_t)o2[1] << 16);
    }

    // A row bases: m16 tile mt covers output row (wid*2 + mt), cols 0..15
    int base0[2];
    #pragma unroll
    for (int mt = 0; mt < 2; mt++)
        base0[mt] = (wid*2 + mt)*2*PSTR + 2*g;

    float acc[2][8][4];
    #pragma unroll
    for (int mt = 0; mt < 2; mt++)
        #pragma unroll
        for (int nt = 0; nt < 8; nt++)
            #pragma unroll
            for (int r = 0; r < 4; r++) acc[mt][nt][r] = 0.f;

    auto stage = [&](int gr, int bufi) {
        const float4* ws = (const float4*)(g_wt + ((size_t)(b*NST + gr))*WBUF);
        const uint32_t wdst = w_base + (uint32_t)bufi*(WBUF*4);
        for (int i = tid; i < WBUF/4; i += 256)     // 1664 float4
            cp_async16(wdst + (uint32_t)i*16u, ws + i);
        #pragma unroll
        for (int j = 0; j < NSLOT; j++) {
            uint32_t so = (sP[j>>1] >> ((j&1)*16)) & 0xFFFFu;
            uint32_t go = (gP[j>>1] >> ((j&1)*16)) & 0xFFFFu;
            int sz = ((vmask >> j) & 1u) ? 4 : 0;
            uint32_t d0 = p_base + (uint32_t)bufi*(PBUF*4) + so*4u;
            #pragma unroll
            for (int icl = 0; icl < GIC; icl++)
                cp_async4(d0 + (uint32_t)icl*(PICF*4),
                          xb + (size_t)(gr*GIC + icl)*(HH*WW) + go, sz);
        }
        asm volatile("cp.async.commit_group;" ::: "memory");
    };

    stage(0, 0);
    asm volatile("cp.async.wait_group 0;" ::: "memory");
    __syncthreads();

    for (int gr = 0; gr < NST; gr++) {
        const int cur = gr & 1;
        if (gr + 1 < NST) stage(gr + 1, cur ^ 1);

        const float* wbuf = s_w + cur*WBUF;
        const float* pbuf = s_p + cur*PBUF;
        #pragma unroll
        for (int s = 0; s < NKS; s++) {
            // B fragments: [s][oc][tig][h], oc = nt*8 + g; coalesced LDS.64
            const float* wr = wbuf + ((s*64 + g)*4 + tig)*2;
            uint32_t b0[8], b1[8];
            #pragma unroll
            for (int nt = 0; nt < 8; nt++) {
                float2 w2 = *(const float2*)&wr[nt*64];
                b0[nt] = __float_as_uint(w2.x);
                b1[nt] = __float_as_uint(w2.y);
            }
            const int o0 = (int)(offP[s] & 0xFFFFu);
            const int o1 = (int)(offP[s] >> 16);
            #pragma unroll
            for (int mt = 0; mt < 2; mt++) {
                uint32_t a0 = cvt_tf32(*(const uint32_t*)&pbuf[base0[mt] + o0]);
                uint32_t a1 = cvt_tf32(*(const uint32_t*)&pbuf[base0[mt] + 16 + o0]);
                uint32_t a2 = cvt_tf32(*(const uint32_t*)&pbuf[base0[mt] + o1]);
                uint32_t a3 = cvt_tf32(*(const uint32_t*)&pbuf[base0[mt] + 16 + o1]);
                #pragma unroll
                for (int nt = 0; nt < 8; nt++) {
                    asm volatile(
                        "mma.sync.aligned.m16n8k8.row.col.f32.tf32.tf32.f32 "
                        "{%0,%1,%2,%3}, {%4,%5,%6,%7}, {%8,%9}, {%0,%1,%2,%3};"
                        : "+f"(acc[mt][nt][0]), "+f"(acc[mt][nt][1]),
                          "+f"(acc[mt][nt][2]), "+f"(acc[mt][nt][3])
                        : "r"(a0), "r"(a1), "r"(a2), "r"(a3), "r"(b0[nt]), "r"(b1[nt]));
                }
            }
        }
        asm volatile("cp.async.wait_group 0;" ::: "memory");
        __syncthreads();
    }

    // ---- writeout: m16 tile mt = output row (wid*2+mt); frag rows g/g+8 = cols ----
    #pragma unroll
    for (int mt = 0; mt < 2; mt++) {
        const int oy = oy0 + wid*2 + mt;
        #pragma unroll
        for (int nt = 0; nt < 8; nt++) {
            const int oc = nt*8 + 2*tig;
            const float bz0 = s_bias[oc], bz1 = s_bias[oc + 1];
            #pragma unroll
            for (int h = 0; h < 2; h++) {
                const int ox = ox0 + g + 8*h;
                if (oy < HO && ox < WO) {
                    size_t o_idx = ((size_t)(b*64 + oc))*NPIX + (size_t)oy*WO + ox;
                    out[o_idx]        = acc[mt][nt][2*h]     + bz0;
                    out[o_idx + NPIX] = acc[mt][nt][2*h + 1] + bz1;
                }
            }
        }
    }
}

extern "C" void kernel_launch(void* const* d_in, const int* in_sizes, int n_in,
                              void* d_out, int out_size) {
    const float* x      = (const float*)d_in[0];
    const float* fc1_w  = (const float*)d_in[1];
    const float* fc1_b  = (const float*)d_in[2];
    const float* fc2_w  = (const float*)d_in[3];
    const float* fc2_b  = (const float*)d_in[4];
    const float* weight = (const float*)d_in[5];
    const float* bias   = (const float*)d_in[6];
    float* out = (float*)d_out;

    cudaFuncSetAttribute(conv_mma_kernel,
                         cudaFuncAttributeMaxDynamicSharedMemorySize, SMEM_BYTES);

    pool_kernel<<<BB*DIM, 256>>>(x);
    att_kernel<<<1, 64>>>(fc1_w, fc1_b, fc2_w, fc2_b);
    wt_fill_kernel<<<(BB*NST*WBUF)/256, 256>>>(weight, out);
    dim3 grid((WO + TW - 1)/TW, (HO + TH - 1)/TH, BB);
    conv_mma_kernel<<<grid, 256, SMEM_BYTES>>>(x, bias, out);
}